// round 5
// baseline (speedup 1.0000x reference)
#include <cuda_runtime.h>
#include <cuda_bf16.h>
#include <cstdint>
#include <math.h>

#define BATCH  4
#define SEQ    4096
#define DMODEL 1024
#define DH     64
#define NCHUNK 8
#define ATTN_BLOCKS 1152

// ---------------------------------------------------------------------------
// Scratch (device globals, no allocation)
// ---------------------------------------------------------------------------
__device__ float g_qh[BATCH * SEQ * DH];
__device__ float g_kh[BATCH * SEQ * DH];
__device__ float g_vh[BATCH * SEQ * DH];
__device__ float g_po[NCHUNK][BATCH * SEQ * DH];
__device__ float g_pm[NCHUNK][BATCH * SEQ];
__device__ float g_pl[NCHUNK][BATCH * SEQ];

// W in bf16 hi/lo, packed as bf16x2 words: [which][n][k/2], 3*64*512 words.
__device__ uint32_t g_wh[3 * 64 * 512];
__device__ uint32_t g_wl[3 * 64 * 512];

__device__ __forceinline__ int swz4(int kk) { return ((kk >> 2) & 7) << 2; }

// bf16 m16n8k16 MMA (HMMA path — works on plain sm_103 target)
__device__ __forceinline__ void mma16816(float c[4], const uint32_t a[4],
                                         uint32_t b0, uint32_t b1) {
    asm volatile(
        "mma.sync.aligned.m16n8k16.row.col.f32.bf16.bf16.f32 "
        "{%0,%1,%2,%3}, {%4,%5,%6,%7}, {%8,%9}, {%0,%1,%2,%3};"
        : "+f"(c[0]), "+f"(c[1]), "+f"(c[2]), "+f"(c[3])
        : "r"(a[0]), "r"(a[1]), "r"(a[2]), "r"(a[3]), "r"(b0), "r"(b1));
}

__device__ __forceinline__ uint32_t cvt_hi(float2 f) {
    __nv_bfloat162 h = __floats2bfloat162_rn(f.x, f.y);
    return *(uint32_t*)&h;
}
__device__ __forceinline__ uint32_t cvt_lo(float2 f, uint32_t hi) {
    __nv_bfloat162 h = *(__nv_bfloat162*)&hi;
    __nv_bfloat162 l = __floats2bfloat162_rn(f.x - __low2float(h),
                                             f.y - __high2float(h));
    return *(uint32_t*)&l;
}

// ---------------------------------------------------------------------------
// One-time W conversion: fp32 -> bf16 hi/lo (768 KB total, ~3 us)
// ---------------------------------------------------------------------------
__global__ __launch_bounds__(256)
void wconv_kernel(const float* __restrict__ wq, const float* __restrict__ wk,
                  const float* __restrict__ wv)
{
    const int t = blockIdx.x * 256 + threadIdx.x;      // 0 .. 3*32768-1
    const int which = t >> 15;
    const int p = t & 32767;                           // bf16x2 word index
    const float* w = (which == 0) ? wq : (which == 1) ? wk : wv;
    float2 f = *(const float2*)(w + 2 * p);
    uint32_t h = cvt_hi(f);
    g_wh[t] = h;
    g_wl[t] = cvt_lo(f, h);
}

// ---------------------------------------------------------------------------
// Projection via mma.sync: out[row][n] = sum_k x[row][k]*W[n][k] + b[n]
// Block: 256 thr = 8 warps, each warp 16 rows x 64 cols. No smem.
// hi/lo split: 3 MMAs per (kstep, ntile).
// ---------------------------------------------------------------------------
__global__ __launch_bounds__(256)
void proj_mma_kernel(const float* __restrict__ qin, const float* __restrict__ kin,
                     const float* __restrict__ vin,
                     const float* __restrict__ bq, const float* __restrict__ bk,
                     const float* __restrict__ bv)
{
    const int which = blockIdx.y;
    const float* __restrict__ x    = (which == 0) ? qin : (which == 1) ? kin : vin;
    const float* __restrict__ bias = (which == 0) ? bq  : (which == 1) ? bk  : bv;
    float* __restrict__ out        = (which == 0) ? g_qh : (which == 1) ? g_kh : g_vh;
    const uint32_t* __restrict__ wh = g_wh + which * 32768;
    const uint32_t* __restrict__ wl = g_wl + which * 32768;

    const int warp = threadIdx.x >> 5;
    const int lane = threadIdx.x & 31;
    const int gid  = lane >> 2;      // 0..7
    const int tig  = lane & 3;       // 0..3
    const int row  = blockIdx.x * 128 + warp * 16 + gid;

    const float* xr0 = x + (size_t)row * DMODEL;
    const float* xr1 = xr0 + 8 * DMODEL;

    float c[8][4] = {};

    #pragma unroll 4
    for (int ks = 0; ks < 64; ks++) {
        const int kb = ks * 16;
        float2 f0 = *(const float2*)(xr0 + kb + 2 * tig);
        float2 f1 = *(const float2*)(xr1 + kb + 2 * tig);
        float2 f2 = *(const float2*)(xr0 + kb + 2 * tig + 8);
        float2 f3 = *(const float2*)(xr1 + kb + 2 * tig + 8);

        uint32_t ah[4], al[4];
        ah[0] = cvt_hi(f0); al[0] = cvt_lo(f0, ah[0]);
        ah[1] = cvt_hi(f1); al[1] = cvt_lo(f1, ah[1]);
        ah[2] = cvt_hi(f2); al[2] = cvt_lo(f2, ah[2]);
        ah[3] = cvt_hi(f3); al[3] = cvt_lo(f3, ah[3]);

        const int wb = (kb >> 1) + tig;   // bf16x2 word offset within 512-word row
        #pragma unroll
        for (int nt = 0; nt < 8; nt++) {
            const int n = nt * 8 + gid;
            const uint32_t* whp = wh + n * 512 + wb;
            const uint32_t* wlp = wl + n * 512 + wb;
            const uint32_t bh0 = whp[0], bh1 = whp[4];
            const uint32_t bl0 = wlp[0], bl1 = wlp[4];
            mma16816(c[nt], ah, bh0, bh1);   // hi*hi
            mma16816(c[nt], ah, bl0, bl1);   // hi*lo
            mma16816(c[nt], al, bh0, bh1);   // lo*hi
        }
    }

    // Epilogue: add bias, store. c0/c1 -> (row, col..col+1), c2/c3 -> row+8.
    #pragma unroll
    for (int nt = 0; nt < 8; nt++) {
        const int col = nt * 8 + 2 * tig;
        const float b0 = bias[col], b1 = bias[col + 1];
        *(float2*)(out + (size_t)row * DH + col) =
            make_float2(c[nt][0] + b0, c[nt][1] + b1);
        *(float2*)(out + (size_t)(row + 8) * DH + col) =
            make_float2(c[nt][2] + b0, c[nt][3] + b1);
    }
}

// ---------------------------------------------------------------------------
// Causal flash attention with split-KV (fp32 CUDA cores) — proven kernel.
// ---------------------------------------------------------------------------
__global__ __launch_bounds__(256, 3)
void attn_kernel()
{
    __shared__ float Qs[64 * 64];
    __shared__ float Ks[64 * 64];
    __shared__ float Vs[64 * 64];

    const int tid = threadIdx.x;
    const int ty = tid >> 4;
    const int tx = tid & 15;

    const int gid = (ATTN_BLOCKS - 1) - blockIdx.x;
    const int b   = gid / 288;
    const int r   = gid - b * 288;
    int a = 0;
    #pragma unroll
    for (int t = 1; t < 8; t++)
        if (4 * t * (t + 1) <= r) a = t;
    const int rr = r - 4 * a * (a + 1);
    const int qt = 8 * a + rr / (a + 1);
    const int c  = rr - (rr / (a + 1)) * (a + 1);

    const int q0  = qt * 64;
    const int kt0 = c * 8;
    const int kt1 = min(kt0 + 7, qt);

    const float* __restrict__ qh = g_qh + (size_t)b * SEQ * DH;
    const float* __restrict__ kh = g_kh + (size_t)b * SEQ * DH;
    const float* __restrict__ vh = g_vh + (size_t)b * SEQ * DH;

    #pragma unroll
    for (int it = 0; it < 4; it++) {
        const int f = it * 256 + tid;
        const int rq = f >> 4;
        const int cc = (f & 15) << 2;
        const int sw = swz4(cc);
        float4 v = *(const float4*)(qh + (size_t)(q0 + rq) * DH + cc);
        Qs[(cc + 0) * 64 + (rq ^ sw)] = v.x;
        Qs[(cc + 1) * 64 + (rq ^ sw)] = v.y;
        Qs[(cc + 2) * 64 + (rq ^ sw)] = v.z;
        Qs[(cc + 3) * 64 + (rq ^ sw)] = v.w;
    }

    float o[4][4] = {};
    float m[4] = {-3.0e38f, -3.0e38f, -3.0e38f, -3.0e38f};
    float l[4] = {};

    for (int kt = kt0; kt <= kt1; kt++) {
        const int k0 = kt * 64;
        __syncthreads();
        #pragma unroll
        for (int it = 0; it < 4; it++) {
            const int f = it * 256 + tid;
            const int rk = f >> 4;
            const int cc = (f & 15) << 2;
            const int sw = swz4(cc);
            float4 kv = *(const float4*)(kh + (size_t)(k0 + rk) * DH + cc);
            Ks[(cc + 0) * 64 + (rk ^ sw)] = kv.x;
            Ks[(cc + 1) * 64 + (rk ^ sw)] = kv.y;
            Ks[(cc + 2) * 64 + (rk ^ sw)] = kv.z;
            Ks[(cc + 3) * 64 + (rk ^ sw)] = kv.w;
            float4 vv = *(const float4*)(vh + (size_t)(k0 + rk) * DH + cc);
            *(float4*)(Vs + rk * 64 + cc) = vv;
        }
        __syncthreads();

        float s[4][4] = {};
        #pragma unroll
        for (int kk = 0; kk < 64; kk++) {
            const int sw = swz4(kk);
            float4 aa = *(const float4*)(Qs + kk * 64 + ((ty << 2) ^ sw));
            float4 bk4 = *(const float4*)(Ks + kk * 64 + ((tx << 2) ^ sw));
            float av[4] = {aa.x, aa.y, aa.z, aa.w};
            float bw[4] = {bk4.x, bk4.y, bk4.z, bk4.w};
            #pragma unroll
            for (int i = 0; i < 4; i++)
                #pragma unroll
                for (int j = 0; j < 4; j++)
                    s[i][j] = fmaf(av[i], bw[j], s[i][j]);
        }

        if (kt == qt) {
            #pragma unroll
            for (int i = 0; i < 4; i++)
                #pragma unroll
                for (int j = 0; j < 4; j++) {
                    const bool masked = (k0 + (tx << 2) + j) > (q0 + (ty << 2) + i);
                    s[i][j] = masked ? -1.0e30f : s[i][j] * 0.125f;
                }
        } else {
            #pragma unroll
            for (int i = 0; i < 4; i++)
                #pragma unroll
                for (int j = 0; j < 4; j++)
                    s[i][j] *= 0.125f;
        }

        #pragma unroll
        for (int i = 0; i < 4; i++) {
            float rmax = fmaxf(fmaxf(s[i][0], s[i][1]), fmaxf(s[i][2], s[i][3]));
            rmax = fmaxf(rmax, __shfl_xor_sync(0xffffffffu, rmax, 8));
            rmax = fmaxf(rmax, __shfl_xor_sync(0xffffffffu, rmax, 4));
            rmax = fmaxf(rmax, __shfl_xor_sync(0xffffffffu, rmax, 2));
            rmax = fmaxf(rmax, __shfl_xor_sync(0xffffffffu, rmax, 1));
            const float mn = fmaxf(m[i], rmax);
            const float alpha = __expf(m[i] - mn);
            m[i] = mn;
            #pragma unroll
            for (int j = 0; j < 4; j++)
                s[i][j] = __expf(s[i][j] - mn);
            l[i] = l[i] * alpha + (s[i][0] + s[i][1] + s[i][2] + s[i][3]);
            #pragma unroll
            for (int j = 0; j < 4; j++)
                o[i][j] *= alpha;
        }

        __syncthreads();
        #pragma unroll
        for (int j = 0; j < 4; j++) {
            const int kcol = (tx << 2) + j;
            const int sw = swz4(kcol);
            #pragma unroll
            for (int i = 0; i < 4; i++)
                Ks[kcol * 64 + (((ty << 2) + i) ^ sw)] = s[i][j];
        }
        __syncthreads();

        #pragma unroll
        for (int kk = 0; kk < 64; kk++) {
            const int sw = swz4(kk);
            float4 aa = *(const float4*)(Ks + kk * 64 + ((ty << 2) ^ sw));
            float4 bv4 = *(const float4*)(Vs + kk * 64 + (tx << 2));
            float av[4] = {aa.x, aa.y, aa.z, aa.w};
            float bw[4] = {bv4.x, bv4.y, bv4.z, bv4.w};
            #pragma unroll
            for (int i = 0; i < 4; i++)
                #pragma unroll
                for (int j = 0; j < 4; j++)
                    o[i][j] = fmaf(av[i], bw[j], o[i][j]);
        }
    }

    #pragma unroll
    for (int i = 0; i < 4; i++) {
        float li = l[i];
        li += __shfl_xor_sync(0xffffffffu, li, 8);
        li += __shfl_xor_sync(0xffffffffu, li, 4);
        li += __shfl_xor_sync(0xffffffffu, li, 2);
        li += __shfl_xor_sync(0xffffffffu, li, 1);
        const int row = b * SEQ + q0 + (ty << 2) + i;
        *(float4*)&g_po[c][(size_t)row * DH + (tx << 2)] =
            make_float4(o[i][0], o[i][1], o[i][2], o[i][3]);
        if (tx == 0) {
            g_pm[c][row] = m[i];
            g_pl[c][row] = li;
        }
    }
}

// ---------------------------------------------------------------------------
__global__ __launch_bounds__(256)
void merge_kernel(float* __restrict__ out)
{
    const int t = blockIdx.x * 256 + threadIdx.x;
    const int row = t >> 4;
    const int cg  = (t & 15) << 2;
    const int q   = row & (SEQ - 1);
    const int nc  = ((q >> 6) >> 3) + 1;

    float mstar = -3.0e38f;
    #pragma unroll 4
    for (int c = 0; c < nc; c++)
        mstar = fmaxf(mstar, g_pm[c][row]);

    float L = 0.0f;
    float4 acc = make_float4(0.f, 0.f, 0.f, 0.f);
    #pragma unroll 4
    for (int c = 0; c < nc; c++) {
        const float wgt = __expf(g_pm[c][row] - mstar);
        L += wgt * g_pl[c][row];
        float4 ov = *(const float4*)&g_po[c][(size_t)row * DH + cg];
        acc.x += wgt * ov.x; acc.y += wgt * ov.y;
        acc.z += wgt * ov.z; acc.w += wgt * ov.w;
    }
    const float inv = 1.0f / L;
    *(float4*)(out + (size_t)row * DH + cg) =
        make_float4(acc.x * inv, acc.y * inv, acc.z * inv, acc.w * inv);
}

// ---------------------------------------------------------------------------
extern "C" void kernel_launch(void* const* d_in, const int* in_sizes, int n_in,
                              void* d_out, int out_size)
{
    (void)in_sizes; (void)n_in; (void)out_size;
    const float* q  = (const float*)d_in[0];
    const float* k  = (const float*)d_in[1];
    const float* v  = (const float*)d_in[2];
    const float* wq = (const float*)d_in[3];
    const float* bq = (const float*)d_in[4];
    const float* wk = (const float*)d_in[5];
    const float* bk = (const float*)d_in[6];
    const float* wv = (const float*)d_in[7];
    const float* bv = (const float*)d_in[8];
    float* out = (float*)d_out;

    wconv_kernel<<<384, 256>>>(wq, wk, wv);
    dim3 pgrid(BATCH * SEQ / 128, 3);   // (128, 3)
    proj_mma_kernel<<<pgrid, 256>>>(q, k, v, bq, bk, bv);
    attn_kernel<<<ATTN_BLOCKS, 256>>>();
    merge_kernel<<<BATCH * SEQ * 16 / 256, 256>>>(out);
}

// round 6
// speedup vs baseline: 2.1684x; 2.1684x over previous
#include <cuda_runtime.h>
#include <cuda_bf16.h>
#include <cstdint>
#include <math.h>

#define BATCH  4
#define SEQ    4096
#define DMODEL 1024
#define DH     64
#define NCHUNK 8
#define ATTN_BLOCKS 1152

// ---------------------------------------------------------------------------
// Scratch (device globals, no allocation)
// ---------------------------------------------------------------------------
__device__ float g_qh[BATCH * SEQ * DH];
__device__ float g_kh[BATCH * SEQ * DH];
__device__ float g_vh[BATCH * SEQ * DH];
__device__ float g_po[NCHUNK][BATCH * SEQ * DH];
__device__ float g_pm[NCHUNK][BATCH * SEQ];
__device__ float g_pl[NCHUNK][BATCH * SEQ];
// W in bf16 hi/lo, bf16x2 words: [which][n][k/2]
__device__ uint32_t g_wh[3 * 64 * 512];
__device__ uint32_t g_wl[3 * 64 * 512];

// ---------------------------------------------------------------------------
// mma.sync helpers (conventions proven in round 5)
// ---------------------------------------------------------------------------
__device__ __forceinline__ void mma16816(float c[4], const uint32_t a[4],
                                         uint32_t b0, uint32_t b1) {
    asm volatile(
        "mma.sync.aligned.m16n8k16.row.col.f32.bf16.bf16.f32 "
        "{%0,%1,%2,%3}, {%4,%5,%6,%7}, {%8,%9}, {%0,%1,%2,%3};"
        : "+f"(c[0]), "+f"(c[1]), "+f"(c[2]), "+f"(c[3])
        : "r"(a[0]), "r"(a[1]), "r"(a[2]), "r"(a[3]), "r"(b0), "r"(b1));
}
__device__ __forceinline__ uint32_t cvt_hi(float2 f) {
    __nv_bfloat162 h = __floats2bfloat162_rn(f.x, f.y);
    return *(uint32_t*)&h;
}
__device__ __forceinline__ uint32_t cvt_lo(float2 f, uint32_t hi) {
    __nv_bfloat162 h = *(__nv_bfloat162*)&hi;
    __nv_bfloat162 l = __floats2bfloat162_rn(f.x - __low2float(h),
                                             f.y - __high2float(h));
    return *(uint32_t*)&l;
}

// FMA-pipe exp (no MUFU): exp(x) for x <= 0, exact-enough to ~2e-6 rel.
__device__ __forceinline__ float fast_exp(float x) {
    x = fmaxf(x, -87.0f);
    const float L2E = 1.4426950408889634f;
    float ys = fmaf(x, L2E, 12582912.0f);            // round-to-int via magic
    int   n  = __float_as_int(ys) - 0x4B400000;      // integer part
    float nf = ys - 12582912.0f;
    float f  = fmaf(x, L2E, -nf);                    // frac in [-0.5, 0.5]
    float p  = 1.3298820e-3f;                        // 2^f Taylor (ln2 powers)
    p = fmaf(p, f, 9.6181291e-3f);
    p = fmaf(p, f, 5.5504109e-2f);
    p = fmaf(p, f, 2.4022649e-1f);
    p = fmaf(p, f, 6.9314718e-1f);
    p = fmaf(p, f, 1.0f);
    return __int_as_float((n + 127) << 23) * p;      // 2^n * 2^f
}

// ---------------------------------------------------------------------------
// One-time W conversion: fp32 -> bf16 hi/lo
// ---------------------------------------------------------------------------
__global__ __launch_bounds__(256)
void wconv_kernel(const float* __restrict__ wq, const float* __restrict__ wk,
                  const float* __restrict__ wv)
{
    const int t = blockIdx.x * 256 + threadIdx.x;
    const int which = t >> 15;
    const int p = t & 32767;
    const float* w = (which == 0) ? wq : (which == 1) ? wk : wv;
    float2 f = *(const float2*)(w + 2 * p);
    uint32_t h = cvt_hi(f);
    g_wh[t] = h;
    g_wl[t] = cvt_lo(f, h);
}

// ---------------------------------------------------------------------------
// Projection: smem-staged HMMA. Block = 64 rows x 64 n, 4 warps.
// Word layout [r][k2] with stride 36 -> conflict-free fragment LDS.
// ---------------------------------------------------------------------------
__global__ __launch_bounds__(128)
void proj_mma_kernel(const float* __restrict__ qin, const float* __restrict__ kin,
                     const float* __restrict__ vin,
                     const float* __restrict__ bq, const float* __restrict__ bk,
                     const float* __restrict__ bv)
{
    __shared__ uint32_t Xh[64 * 36], Xl[64 * 36];
    __shared__ uint32_t Wh[64 * 36], Wl[64 * 36];

    const int which = blockIdx.y;
    const float* __restrict__ x    = (which == 0) ? qin : (which == 1) ? kin : vin;
    const float* __restrict__ bias = (which == 0) ? bq  : (which == 1) ? bk  : bv;
    float* __restrict__ out        = (which == 0) ? g_qh : (which == 1) ? g_kh : g_vh;
    const uint32_t* __restrict__ wh = g_wh + which * 32768;
    const uint32_t* __restrict__ wl = g_wl + which * 32768;

    const int tid  = threadIdx.x;
    const int warp = tid >> 5;
    const int lane = tid & 31;
    const int gid  = lane >> 2;
    const int tig  = lane & 3;
    const int row0 = blockIdx.x * 64;

    float acc[8][4] = {};

    for (int kb = 0; kb < 16; kb++) {
        __syncthreads();
        // stage X chunk (64 rows x 64 k) as bf16 hi/lo words
        #pragma unroll
        for (int it = 0; it < 8; it++) {
            const int f = it * 128 + tid;
            const int r = f >> 4;
            const int c4 = (f & 15) << 2;
            float4 v = *(const float4*)(x + (size_t)(row0 + r) * DMODEL + kb * 64 + c4);
            uint32_t h0 = cvt_hi(make_float2(v.x, v.y));
            uint32_t h1 = cvt_hi(make_float2(v.z, v.w));
            uint32_t l0 = cvt_lo(make_float2(v.x, v.y), h0);
            uint32_t l1 = cvt_lo(make_float2(v.z, v.w), h1);
            *(uint2*)&Xh[r * 36 + (c4 >> 1)] = make_uint2(h0, h1);
            *(uint2*)&Xl[r * 36 + (c4 >> 1)] = make_uint2(l0, l1);
        }
        // stage W chunk (64 n x 64 k), already bf16x2 in global
        #pragma unroll
        for (int it = 0; it < 16; it++) {
            const int f = it * 128 + tid;
            const int n = f >> 5;
            const int k2 = f & 31;
            Wh[n * 36 + k2] = wh[n * 512 + kb * 32 + k2];
            Wl[n * 36 + k2] = wl[n * 512 + kb * 32 + k2];
        }
        __syncthreads();

        #pragma unroll
        for (int ks = 0; ks < 4; ks++) {
            const int d2 = (ks << 3) + tig;
            const int ra = (warp << 4) + gid;
            uint32_t ah[4], al[4];
            ah[0] = Xh[ra * 36 + d2];        al[0] = Xl[ra * 36 + d2];
            ah[1] = Xh[(ra + 8) * 36 + d2];  al[1] = Xl[(ra + 8) * 36 + d2];
            ah[2] = Xh[ra * 36 + d2 + 4];    al[2] = Xl[ra * 36 + d2 + 4];
            ah[3] = Xh[(ra + 8) * 36 + d2 + 4]; al[3] = Xl[(ra + 8) * 36 + d2 + 4];
            #pragma unroll
            for (int nt = 0; nt < 8; nt++) {
                const int nr = (nt << 3) + gid;
                const uint32_t bh0 = Wh[nr * 36 + d2], bh1 = Wh[nr * 36 + d2 + 4];
                const uint32_t bl0 = Wl[nr * 36 + d2], bl1 = Wl[nr * 36 + d2 + 4];
                mma16816(acc[nt], ah, bh0, bh1);
                mma16816(acc[nt], ah, bl0, bl1);
                mma16816(acc[nt], al, bh0, bh1);
            }
        }
    }

    const int row = row0 + (warp << 4) + gid;
    #pragma unroll
    for (int nt = 0; nt < 8; nt++) {
        const int col = (nt << 3) + (tig << 1);
        const float b0 = bias[col], b1 = bias[col + 1];
        *(float2*)(out + (size_t)row * DH + col) =
            make_float2(acc[nt][0] + b0, acc[nt][1] + b1);
        *(float2*)(out + (size_t)(row + 8) * DH + col) =
            make_float2(acc[nt][2] + b0, acc[nt][3] + b1);
    }
}

// ---------------------------------------------------------------------------
// Flash attention on mma.sync, split-KV (same decomposition as before).
// Block = 128 threads (4 warps), each warp a 16-q strip of the 64-q tile.
// Q fragments in registers; P reuses S accumulator fragments (no smem trip).
// ---------------------------------------------------------------------------
__global__ __launch_bounds__(128, 3)
void attn_kernel()
{
    __shared__ uint32_t Ksh[64 * 36], Ksl[64 * 36];     // [key][d2], stride 36
    __shared__ uint32_t Vsh[64 * 35], Vsl[64 * 35];     // [d][k2],  stride 35

    const int tid  = threadIdx.x;
    const int warp = tid >> 5;
    const int lane = tid & 31;
    const int gid  = lane >> 2;
    const int tig  = lane & 3;

    const int bgid = (ATTN_BLOCKS - 1) - blockIdx.x;
    const int bb   = bgid / 288;
    const int r    = bgid - bb * 288;
    int a = 0;
    #pragma unroll
    for (int t = 1; t < 8; t++)
        if (4 * t * (t + 1) <= r) a = t;
    const int rr = r - 4 * a * (a + 1);
    const int qt = 8 * a + rr / (a + 1);
    const int ch = rr - (rr / (a + 1)) * (a + 1);

    const int q0  = qt * 64;
    const int kt0 = ch * 8;
    const int kt1 = min(kt0 + 7, qt);

    const float* __restrict__ qh = g_qh + (size_t)bb * SEQ * DH;
    const float* __restrict__ kh = g_kh + (size_t)bb * SEQ * DH;
    const float* __restrict__ vh = g_vh + (size_t)bb * SEQ * DH;

    // Q fragments (hi/lo) in registers, once
    uint32_t qfh[4][4], qfl[4][4];
    {
        const int ra = q0 + (warp << 4) + gid;
        #pragma unroll
        for (int ks = 0; ks < 4; ks++) {
            const float* p0 = qh + (size_t)ra * DH + (ks << 4) + (tig << 1);
            float2 f0 = *(const float2*)(p0);
            float2 f1 = *(const float2*)(p0 + 8 * DH);
            float2 f2 = *(const float2*)(p0 + 8);
            float2 f3 = *(const float2*)(p0 + 8 * DH + 8);
            qfh[ks][0] = cvt_hi(f0); qfl[ks][0] = cvt_lo(f0, qfh[ks][0]);
            qfh[ks][1] = cvt_hi(f1); qfl[ks][1] = cvt_lo(f1, qfh[ks][1]);
            qfh[ks][2] = cvt_hi(f2); qfl[ks][2] = cvt_lo(f2, qfh[ks][2]);
            qfh[ks][3] = cvt_hi(f3); qfl[ks][3] = cvt_lo(f3, qfh[ks][3]);
        }
    }

    float o[8][4] = {};
    float mA = -3.0e38f, mB = -3.0e38f, lA = 0.0f, lB = 0.0f;

    for (int kt = kt0; kt <= kt1; kt++) {
        const int k0 = kt * 64;
        __syncthreads();
        // stage K: [key][d2] bf16x2 hi/lo
        #pragma unroll
        for (int it = 0; it < 8; it++) {
            const int f = it * 128 + tid;
            const int rk = f >> 4;
            const int c4 = (f & 15) << 2;
            float4 v = *(const float4*)(kh + (size_t)(k0 + rk) * DH + c4);
            uint32_t h0 = cvt_hi(make_float2(v.x, v.y));
            uint32_t h1 = cvt_hi(make_float2(v.z, v.w));
            uint32_t l0 = cvt_lo(make_float2(v.x, v.y), h0);
            uint32_t l1 = cvt_lo(make_float2(v.z, v.w), h1);
            *(uint2*)&Ksh[rk * 36 + (c4 >> 1)] = make_uint2(h0, h1);
            *(uint2*)&Ksl[rk * 36 + (c4 >> 1)] = make_uint2(l0, l1);
        }
        // stage V transposed: half at [d*70 + k]
        {
            __nv_bfloat16* vsh = (__nv_bfloat16*)Vsh;
            __nv_bfloat16* vsl = (__nv_bfloat16*)Vsl;
            #pragma unroll
            for (int it = 0; it < 8; it++) {
                const int f = it * 128 + tid;
                const int rk = f >> 4;
                const int c4 = (f & 15) << 2;
                float4 v = *(const float4*)(vh + (size_t)(k0 + rk) * DH + c4);
                float vals[4] = {v.x, v.y, v.z, v.w};
                #pragma unroll
                for (int j = 0; j < 4; j++) {
                    __nv_bfloat16 h = __float2bfloat16(vals[j]);
                    __nv_bfloat16 lo = __float2bfloat16(vals[j] - __bfloat162float(h));
                    vsh[(c4 + j) * 70 + rk] = h;
                    vsl[(c4 + j) * 70 + rk] = lo;
                }
            }
        }
        __syncthreads();

        // S = Q K^T (3-MMA hi/lo split)
        float s[8][4] = {};
        #pragma unroll
        for (int ks = 0; ks < 4; ks++) {
            const int d2 = (ks << 3) + tig;
            #pragma unroll
            for (int nt = 0; nt < 8; nt++) {
                const int kr = (nt << 3) + gid;
                const uint32_t bh0 = Ksh[kr * 36 + d2], bh1 = Ksh[kr * 36 + d2 + 4];
                const uint32_t bl0 = Ksl[kr * 36 + d2], bl1 = Ksl[kr * 36 + d2 + 4];
                mma16816(s[nt], qfh[ks], bh0, bh1);
                mma16816(s[nt], qfh[ks], bl0, bl1);
                mma16816(s[nt], qfl[ks], bh0, bh1);
            }
        }

        // scale + causal mask
        const int rowA = q0 + (warp << 4) + gid;
        const int rowB = rowA + 8;
        if (kt == qt) {
            #pragma unroll
            for (int nt = 0; nt < 8; nt++) {
                const int cb = k0 + (nt << 3) + (tig << 1);
                s[nt][0] = (cb     > rowA) ? -1.0e9f : s[nt][0] * 0.125f;
                s[nt][1] = (cb + 1 > rowA) ? -1.0e9f : s[nt][1] * 0.125f;
                s[nt][2] = (cb     > rowB) ? -1.0e9f : s[nt][2] * 0.125f;
                s[nt][3] = (cb + 1 > rowB) ? -1.0e9f : s[nt][3] * 0.125f;
            }
        } else {
            #pragma unroll
            for (int nt = 0; nt < 8; nt++) {
                s[nt][0] *= 0.125f; s[nt][1] *= 0.125f;
                s[nt][2] *= 0.125f; s[nt][3] *= 0.125f;
            }
        }

        // online softmax (quad owns a row pair)
        float mxA = -3.0e38f, mxB = -3.0e38f;
        #pragma unroll
        for (int nt = 0; nt < 8; nt++) {
            mxA = fmaxf(mxA, fmaxf(s[nt][0], s[nt][1]));
            mxB = fmaxf(mxB, fmaxf(s[nt][2], s[nt][3]));
        }
        mxA = fmaxf(mxA, __shfl_xor_sync(0xffffffffu, mxA, 1));
        mxA = fmaxf(mxA, __shfl_xor_sync(0xffffffffu, mxA, 2));
        mxB = fmaxf(mxB, __shfl_xor_sync(0xffffffffu, mxB, 1));
        mxB = fmaxf(mxB, __shfl_xor_sync(0xffffffffu, mxB, 2));
        const float mnA = fmaxf(mA, mxA), mnB = fmaxf(mB, mxB);
        const float aA = fast_exp(mA - mnA), aB = fast_exp(mB - mnB);
        mA = mnA; mB = mnB;
        float sumA = 0.0f, sumB = 0.0f;
        #pragma unroll
        for (int nt = 0; nt < 8; nt++) {
            s[nt][0] = fast_exp(s[nt][0] - mnA);
            s[nt][1] = fast_exp(s[nt][1] - mnA);
            s[nt][2] = fast_exp(s[nt][2] - mnB);
            s[nt][3] = fast_exp(s[nt][3] - mnB);
            sumA += s[nt][0] + s[nt][1];
            sumB += s[nt][2] + s[nt][3];
        }
        lA = lA * aA + sumA;
        lB = lB * aB + sumB;
        #pragma unroll
        for (int nt = 0; nt < 8; nt++) {
            o[nt][0] *= aA; o[nt][1] *= aA;
            o[nt][2] *= aB; o[nt][3] *= aB;
        }

        // O += P V  (P fragments straight from S accumulators)
        #pragma unroll
        for (int kk = 0; kk < 4; kk++) {
            uint32_t ph[4], pl[4];
            float2 p0 = make_float2(s[2 * kk][0],     s[2 * kk][1]);
            float2 p1 = make_float2(s[2 * kk][2],     s[2 * kk][3]);
            float2 p2 = make_float2(s[2 * kk + 1][0], s[2 * kk + 1][1]);
            float2 p3 = make_float2(s[2 * kk + 1][2], s[2 * kk + 1][3]);
            ph[0] = cvt_hi(p0); pl[0] = cvt_lo(p0, ph[0]);
            ph[1] = cvt_hi(p1); pl[1] = cvt_lo(p1, ph[1]);
            ph[2] = cvt_hi(p2); pl[2] = cvt_lo(p2, ph[2]);
            ph[3] = cvt_hi(p3); pl[3] = cvt_lo(p3, ph[3]);
            const int k2 = (kk << 3) + tig;
            #pragma unroll
            for (int nt = 0; nt < 8; nt++) {
                const int dr = (nt << 3) + gid;
                const uint32_t bh0 = Vsh[dr * 35 + k2], bh1 = Vsh[dr * 35 + k2 + 4];
                const uint32_t bl0 = Vsl[dr * 35 + k2], bl1 = Vsl[dr * 35 + k2 + 4];
                mma16816(o[nt], ph, bh0, bh1);
                mma16816(o[nt], ph, bl0, bl1);
                mma16816(o[nt], pl, bh0, bh1);
            }
        }
    }

    // finalize partials
    lA += __shfl_xor_sync(0xffffffffu, lA, 1);
    lA += __shfl_xor_sync(0xffffffffu, lA, 2);
    lB += __shfl_xor_sync(0xffffffffu, lB, 1);
    lB += __shfl_xor_sync(0xffffffffu, lB, 2);

    const int rowA = bb * SEQ + q0 + (warp << 4) + gid;
    const int rowB = rowA + 8;
    #pragma unroll
    for (int nt = 0; nt < 8; nt++) {
        const int col = (nt << 3) + (tig << 1);
        *(float2*)&g_po[ch][(size_t)rowA * DH + col] = make_float2(o[nt][0], o[nt][1]);
        *(float2*)&g_po[ch][(size_t)rowB * DH + col] = make_float2(o[nt][2], o[nt][3]);
    }
    if (tig == 0) {
        g_pm[ch][rowA] = mA; g_pl[ch][rowA] = lA;
        g_pm[ch][rowB] = mB; g_pl[ch][rowB] = lB;
    }
}

// ---------------------------------------------------------------------------
__global__ __launch_bounds__(256)
void merge_kernel(float* __restrict__ out)
{
    const int t = blockIdx.x * 256 + threadIdx.x;
    const int row = t >> 4;
    const int cg  = (t & 15) << 2;
    const int q   = row & (SEQ - 1);
    const int nc  = ((q >> 6) >> 3) + 1;

    float mstar = -3.0e38f;
    #pragma unroll 4
    for (int c = 0; c < nc; c++)
        mstar = fmaxf(mstar, g_pm[c][row]);

    float L = 0.0f;
    float4 acc = make_float4(0.f, 0.f, 0.f, 0.f);
    #pragma unroll 4
    for (int c = 0; c < nc; c++) {
        const float wgt = __expf(g_pm[c][row] - mstar);
        L += wgt * g_pl[c][row];
        float4 ov = *(const float4*)&g_po[c][(size_t)row * DH + cg];
        acc.x += wgt * ov.x; acc.y += wgt * ov.y;
        acc.z += wgt * ov.z; acc.w += wgt * ov.w;
    }
    const float inv = 1.0f / L;
    *(float4*)(out + (size_t)row * DH + cg) =
        make_float4(acc.x * inv, acc.y * inv, acc.z * inv, acc.w * inv);
}

// ---------------------------------------------------------------------------
extern "C" void kernel_launch(void* const* d_in, const int* in_sizes, int n_in,
                              void* d_out, int out_size)
{
    (void)in_sizes; (void)n_in; (void)out_size;
    const float* q  = (const float*)d_in[0];
    const float* k  = (const float*)d_in[1];
    const float* v  = (const float*)d_in[2];
    const float* wq = (const float*)d_in[3];
    const float* bq = (const float*)d_in[4];
    const float* wk = (const float*)d_in[5];
    const float* bk = (const float*)d_in[6];
    const float* wv = (const float*)d_in[7];
    const float* bv = (const float*)d_in[8];
    float* out = (float*)d_out;

    wconv_kernel<<<384, 256>>>(wq, wk, wv);
    dim3 pgrid(BATCH * SEQ / 64, 3);   // (256, 3)
    proj_mma_kernel<<<pgrid, 128>>>(q, k, v, bq, bk, bv);
    attn_kernel<<<ATTN_BLOCKS, 128>>>();
    merge_kernel<<<BATCH * SEQ * 16 / 256, 256>>>(out);
}